// round 9
// baseline (speedup 1.0000x reference)
#include <cuda_runtime.h>
#include <stdint.h>

#define TT 128
#define MAXB 4096

// ---------------- scratch ----------------
__device__ uint32_t g_h1b[(size_t)MAXB * TT * 32];  // layer1 bidi out, bf16x2 [B][T][32]
__device__ float    g_h2[MAXB * 32];                // layer2 concat [B][32]

// ---------------- helpers ----------------
__device__ __forceinline__ uint32_t bf2(float lo, float hi) {
    uint32_t r;
    asm("cvt.rn.bf16x2.f32 %0, %1, %2;" : "=r"(r) : "f"(hi), "f"(lo));
    return r;
}
__device__ __forceinline__ uint32_t bf2p(float2 v) { return bf2(v.x, v.y); }
__device__ __forceinline__ float tanhx(float x) {
    float y; asm("tanh.approx.f32 %0, %1;" : "=f"(y) : "f"(x)); return y;
}
__device__ __forceinline__ float sigx(float x) {
    return fmaf(tanhx(x * 0.5f), 0.5f, 0.5f);
}
__device__ __forceinline__ void mma_bf16(float* d, const uint4& a, uint32_t b0, uint32_t b1) {
    asm volatile(
        "mma.sync.aligned.m16n8k16.row.col.f32.bf16.bf16.f32 "
        "{%0,%1,%2,%3},{%4,%5,%6,%7},{%8,%9},{%0,%1,%2,%3};"
        : "+f"(d[0]), "+f"(d[1]), "+f"(d[2]), "+f"(d[3])
        : "r"(a.x), "r"(a.y), "r"(a.z), "r"(a.w), "r"(b0), "r"(b1));
}

// ================= layer 1: H=32, KIN=64, K=96 (KC=6), seq out (bf16) ========
// Block = 128 thr = 4 warps; block owns 32 samples = TWO 16-row A tiles.
// grid (B/32, 2). Warp q: gate n-tiles g*4+q for BOTH tiles (48 MMA, 8 chains).
// B fragments in regs (reused across tiles). A double-buffered; one bar/step.
__global__ void __launch_bounds__(128) lstm1_mma(
    const float* __restrict__ in,
    const float* __restrict__ Wf, const float* __restrict__ Uf, const float* __restrict__ bf_,
    const float* __restrict__ Wb, const float* __restrict__ Ub, const float* __restrict__ bb)
{
    __shared__ uint32_t Bsm[6 * 16 * 32 * 2];                // 24KB (init only)
    __shared__ __align__(16) uint32_t Asm[2 * 2 * 6 * 128];  // 12KB: [buf][tile][kc][128]
    __shared__ __align__(16) uint32_t houtS[2 * 2 * 288];    // 4.5KB: [buf][tile][16*18]
    __shared__ float biasS[128];

    const int dir = blockIdx.y;
    const float* W    = dir ? Wb : Wf;
    const float* U    = dir ? Ub : Uf;
    const float* bias = dir ? bb : bf_;

    const int tid = threadIdx.x;
    const int q   = tid >> 5;          // warp id = n-split index = staging kc
    const int l   = tid & 31;
    const int gid = l >> 2;
    const int tig = l & 3;

    // ---- build B fragments (bf16) ----
    for (int idx = tid; idx < 6 * 16 * 32 * 2; idx += 128) {
        const int which = idx & 1;
        const int lane  = (idx >> 1) & 31;
        const int nt    = (idx >> 6) & 15;
        const int kc    = idx >> 10;
        const int k = kc * 16 + which * 8 + 2 * (lane & 3);
        const int n = nt * 8 + (lane >> 2);
        const float v0 = (k     < 64) ? W[k * 128 + n]       : U[(k - 64) * 128 + n];
        const float v1 = (k + 1 < 64) ? W[(k + 1) * 128 + n] : U[(k - 63) * 128 + n];
        Bsm[idx] = bf2(v0, v1);
    }
    if (tid < 128) biasS[tid] = bias[tid];
    // zero h regions of buffer 0, both tiles (kc 4,5)
    for (int idx = tid; idx < 512; idx += 128) {
        const int tau = idx >> 8, ii = idx & 255;
        Asm[tau * 768 + 512 + ii] = 0;
    }
    __syncthreads();

    // ---- B to registers ----
    uint32_t Br[6][4][2];
    #pragma unroll
    for (int kc = 0; kc < 6; kc++)
        #pragma unroll
        for (int g = 0; g < 4; g++) {
            const int base = ((kc * 16 + g * 4 + q) * 32 + l) * 2;
            Br[kc][g][0] = Bsm[base];
            Br[kc][g][1] = Bsm[base + 1];
        }

    float2 bz[4];
    #pragma unroll
    for (int g = 0; g < 4; g++) {
        const int col = g * 32 + q * 8 + 2 * tig;
        bz[g] = make_float2(biasS[col], biasS[col + 1]);
    }

    // ---- staging: warp q stages kc=q for both tiles ----
    const int ws = blockIdx.x * 32;
    const float* xs0[2];
    #pragma unroll
    for (int tau = 0; tau < 2; tau++)
        xs0[tau] = in + (size_t)(ws + tau * 16 + gid) * TT * 64 + q * 16 + 2 * tig;
    // row gid+8 at xs0[tau] + 8*TT*64

    // flush mapping
    const int sF  = tid >> 3;   // 0..15
    const int ocF = tid & 7;

    float cc[2][4] = {{0.f,0.f,0.f,0.f},{0.f,0.f,0.f,0.f}};

    // prologue: stage x_0 into buffer 0, prefetch x_1
    float2 xr[2][4];
    {
        const int tt0 = dir ? TT - 1 : 0;
        #pragma unroll
        for (int tau = 0; tau < 2; tau++) {
            const float* p0 = xs0[tau] + (size_t)tt0 * 64;
            const float* p1 = p0 + (size_t)8 * TT * 64;
            xr[tau][0] = *(const float2*)p0;
            xr[tau][1] = *(const float2*)p1;
            xr[tau][2] = *(const float2*)(p0 + 8);
            xr[tau][3] = *(const float2*)(p1 + 8);
            *(uint4*)(Asm + tau * 768 + q * 128 + l * 4)
                = make_uint4(bf2p(xr[tau][0]), bf2p(xr[tau][1]),
                             bf2p(xr[tau][2]), bf2p(xr[tau][3]));
        }
        const int tt1 = dir ? TT - 2 : 1;
        #pragma unroll
        for (int tau = 0; tau < 2; tau++) {
            const float* p0 = xs0[tau] + (size_t)tt1 * 64;
            const float* p1 = p0 + (size_t)8 * TT * 64;
            xr[tau][0] = *(const float2*)p0;
            xr[tau][1] = *(const float2*)p1;
            xr[tau][2] = *(const float2*)(p0 + 8);
            xr[tau][3] = *(const float2*)(p1 + 8);
        }
    }
    __syncthreads();

    for (int t = 0; t < TT; t++) {
        const int tt = dir ? TT - 1 - t : t;
        const uint32_t* Acur = Asm + (t & 1) * 1536;
        uint32_t*       Anxt = Asm + ((t + 1) & 1) * 1536;

        // ---- MMA on A[t&1]: 2 tiles x 4 gates x 6 kc ----
        float d[2][4][4];
        #pragma unroll
        for (int tau = 0; tau < 2; tau++)
            #pragma unroll
            for (int g = 0; g < 4; g++) {
                d[tau][g][0] = bz[g].x; d[tau][g][1] = bz[g].y;
                d[tau][g][2] = bz[g].x; d[tau][g][3] = bz[g].y;
            }
        #pragma unroll
        for (int kc = 0; kc < 6; kc++) {
            const uint4 a0 = *((const uint4*)Acur + kc * 32 + l);
            const uint4 a1 = *((const uint4*)(Acur + 768) + kc * 32 + l);
            #pragma unroll
            for (int g = 0; g < 4; g++) {
                mma_bf16(d[0][g], a0, Br[kc][g][0], Br[kc][g][1]);
                mma_bf16(d[1][g], a1, Br[kc][g][0], Br[kc][g][1]);
            }
        }

        // ---- flush hout(t-1) (both tiles) ----
        if (t > 0) {
            const int tprev = dir ? tt + 1 : tt - 1;
            #pragma unroll
            for (int tau = 0; tau < 2; tau++) {
                const uint2 hv = *(const uint2*)&houtS[((t - 1) & 1) * 576 + tau * 288 + sF * 18 + ocF * 2];
                *(uint2*)&g_h1b[((size_t)(ws + tau * 16 + sF) * TT + tprev) * 32 + dir * 16 + ocF * 2] = hv;
            }
        }

        // ---- stage x_{t+1} into A[(t+1)&1]; prefetch x_{t+2} ----
        if (t + 1 < TT) {
            #pragma unroll
            for (int tau = 0; tau < 2; tau++)
                *(uint4*)(Anxt + tau * 768 + q * 128 + l * 4)
                    = make_uint4(bf2p(xr[tau][0]), bf2p(xr[tau][1]),
                                 bf2p(xr[tau][2]), bf2p(xr[tau][3]));
            if (t + 2 < TT) {
                const int tt2 = dir ? tt - 2 : tt + 2;
                #pragma unroll
                for (int tau = 0; tau < 2; tau++) {
                    const float* p0 = xs0[tau] + (size_t)tt2 * 64;
                    const float* p1 = p0 + (size_t)8 * TT * 64;
                    xr[tau][0] = *(const float2*)p0;
                    xr[tau][1] = *(const float2*)p1;
                    xr[tau][2] = *(const float2*)(p0 + 8);
                    xr[tau][3] = *(const float2*)(p1 + 8);
                }
            }
        }

        // ---- activations; h -> A[(t+1)&1] + houtS[t&1] ----
        #pragma unroll
        for (int tau = 0; tau < 2; tau++) {
            uint32_t hp[2];
            #pragma unroll
            for (int rh = 0; rh < 2; rh++) {
                float h0, h1;
                {
                    const int p = rh * 2;
                    const float ig = sigx(d[tau][0][p]);
                    const float fg = sigx(d[tau][1][p]);
                    const float gg = tanhx(d[tau][2][p]);
                    const float og = sigx(d[tau][3][p]);
                    const float c  = fg * cc[tau][p] + ig * gg;
                    h0 = og * tanhx(c); cc[tau][p] = c;
                }
                {
                    const int p = rh * 2 + 1;
                    const float ig = sigx(d[tau][0][p]);
                    const float fg = sigx(d[tau][1][p]);
                    const float gg = tanhx(d[tau][2][p]);
                    const float og = sigx(d[tau][3][p]);
                    const float c  = fg * cc[tau][p] + ig * gg;
                    h1 = og * tanhx(c); cc[tau][p] = c;
                }
                hp[rh] = bf2(h0, h1);
                houtS[(t & 1) * 576 + tau * 288 + (gid + 8 * rh) * 18 + q * 4 + tig] = hp[rh];
            }
            *(uint2*)(Anxt + tau * 768 + (4 + (q >> 1)) * 128 + l * 4 + (q & 1) * 2)
                = make_uint2(hp[0], hp[1]);
        }

        __syncthreads();
    }

    // final flush (t = TT-1)
    {
        const int tlast = dir ? 0 : TT - 1;
        #pragma unroll
        for (int tau = 0; tau < 2; tau++) {
            const uint2 hv = *(const uint2*)&houtS[((TT - 1) & 1) * 576 + tau * 288 + sF * 18 + ocF * 2];
            *(uint2*)&g_h1b[((size_t)(ws + tau * 16 + sF) * TT + tlast) * 32 + dir * 16 + ocF * 2] = hv;
        }
    }
}

// ================= layer 2: H=16, KIN=64, K=80 (KC=5), last-h only ===========
// Block = 64 thr = 2 warps; block owns 32 samples = TWO 16-row A tiles.
// grid (B/32, 2). Warp half: gate n-tiles g*2+half for BOTH tiles (40 MMA,
// 8 chains). B in regs. A double-buffered; one __syncthreads per step.
// Staging reads g_h1b (bf16): pure u32 copies.
__global__ void __launch_bounds__(64) lstm2_mma(
    const float* __restrict__ W2f, const float* __restrict__ U2f, const float* __restrict__ b2f,
    const float* __restrict__ W2b, const float* __restrict__ U2b, const float* __restrict__ b2b)
{
    __shared__ uint32_t Bsm[5 * 8 * 32 * 2];                 // 10KB (init only)
    __shared__ __align__(16) uint32_t Asm[2 * 2 * 5 * 128];  // 10KB: [buf][tile][kc][128]
    __shared__ float biasS[64];

    const int dir = blockIdx.y;
    const float* W    = dir ? W2b : W2f;
    const float* U    = dir ? U2b : U2f;
    const float* bias = dir ? b2b : b2f;

    const int tid  = threadIdx.x;
    const int half = tid >> 5;
    const int l    = tid & 31;
    const int gid  = l >> 2;
    const int tig  = l & 3;

    for (int idx = tid; idx < 5 * 8 * 32 * 2; idx += 64) {
        const int which = idx & 1;
        const int lane  = (idx >> 1) & 31;
        const int nt    = (idx >> 6) & 7;
        const int kc    = idx >> 9;
        const int k = kc * 16 + which * 8 + 2 * (lane & 3);
        const int n = nt * 8 + (lane >> 2);
        const float v0 = (k     < 64) ? W[k * 64 + n]       : U[(k - 64) * 64 + n];
        const float v1 = (k + 1 < 64) ? W[(k + 1) * 64 + n] : U[(k - 63) * 64 + n];
        Bsm[idx] = bf2(v0, v1);
    }
    if (tid < 64) biasS[tid] = bias[tid];
    // zero h regions of buffer 0, both tiles (kc 4)
    for (int idx = tid; idx < 256; idx += 64) {
        const int tau = idx >> 7, ii = idx & 127;
        Asm[tau * 640 + 512 + ii] = 0;
    }
    __syncthreads();

    uint32_t Br[5][4][2];
    #pragma unroll
    for (int kc = 0; kc < 5; kc++)
        #pragma unroll
        for (int g = 0; g < 4; g++) {
            const int base = ((kc * 8 + g * 2 + half) * 32 + l) * 2;
            Br[kc][g][0] = Bsm[base];
            Br[kc][g][1] = Bsm[base + 1];
        }

    float2 bz[4];
    #pragma unroll
    for (int g = 0; g < 4; g++) {
        const int col = g * 16 + half * 8 + 2 * tig;
        bz[g] = make_float2(biasS[col], biasS[col + 1]);
    }

    const int ws = blockIdx.x * 32;

    // staging: thread tid (0-63) -> kcS (0-3), gidS (0-7), tp (0-1), x2 tiles
    const int kcS  = tid >> 4;
    const int gidS = (tid & 15) >> 1;
    const int tp   = tid & 1;
    const int j0   = gidS * 4 + 2 * tp;
    const uint32_t* h0p[2];
    #pragma unroll
    for (int tau = 0; tau < 2; tau++)
        h0p[tau] = g_h1b + (size_t)(ws + tau * 16 + gidS) * TT * 32 + kcS * 8 + 2 * tp;
    // row gidS+8 at h0p[tau] + 8*TT*32

    float cc[2][4] = {{0.f,0.f,0.f,0.f},{0.f,0.f,0.f,0.f}};

    uint2 lo0[2], lo1[2], hi0[2], hi1[2];
    {
        const int tt0 = dir ? TT - 1 : 0;
        #pragma unroll
        for (int tau = 0; tau < 2; tau++) {
            const uint32_t* p0 = h0p[tau] + (size_t)tt0 * 32;
            const uint32_t* p1 = p0 + (size_t)8 * TT * 32;
            lo0[tau] = *(const uint2*)p0;
            lo1[tau] = *(const uint2*)p1;
            hi0[tau] = *(const uint2*)(p0 + 4);
            hi1[tau] = *(const uint2*)(p1 + 4);
            *(uint4*)(Asm + tau * 640 + kcS * 128 + j0 * 4)
                = make_uint4(lo0[tau].x, lo1[tau].x, hi0[tau].x, hi1[tau].x);
            *(uint4*)(Asm + tau * 640 + kcS * 128 + (j0 + 1) * 4)
                = make_uint4(lo0[tau].y, lo1[tau].y, hi0[tau].y, hi1[tau].y);
        }
        const int tt1 = dir ? TT - 2 : 1;
        #pragma unroll
        for (int tau = 0; tau < 2; tau++) {
            const uint32_t* p0 = h0p[tau] + (size_t)tt1 * 32;
            const uint32_t* p1 = p0 + (size_t)8 * TT * 32;
            lo0[tau] = *(const uint2*)p0;
            lo1[tau] = *(const uint2*)p1;
            hi0[tau] = *(const uint2*)(p0 + 4);
            hi1[tau] = *(const uint2*)(p1 + 4);
        }
    }
    __syncthreads();

    for (int t = 0; t < TT; t++) {
        const int tt = dir ? TT - 1 - t : t;
        const uint32_t* Acur = Asm + (t & 1) * 1280;
        uint32_t*       Anxt = Asm + ((t + 1) & 1) * 1280;

        float d[2][4][4];
        #pragma unroll
        for (int tau = 0; tau < 2; tau++)
            #pragma unroll
            for (int g = 0; g < 4; g++) {
                d[tau][g][0] = bz[g].x; d[tau][g][1] = bz[g].y;
                d[tau][g][2] = bz[g].x; d[tau][g][3] = bz[g].y;
            }
        #pragma unroll
        for (int kc = 0; kc < 5; kc++) {
            const uint4 a0 = *((const uint4*)Acur + kc * 32 + l);
            const uint4 a1 = *((const uint4*)(Acur + 640) + kc * 32 + l);
            #pragma unroll
            for (int g = 0; g < 4; g++) {
                mma_bf16(d[0][g], a0, Br[kc][g][0], Br[kc][g][1]);
                mma_bf16(d[1][g], a1, Br[kc][g][0], Br[kc][g][1]);
            }
        }

        if (t + 1 < TT) {
            #pragma unroll
            for (int tau = 0; tau < 2; tau++) {
                *(uint4*)(Anxt + tau * 640 + kcS * 128 + j0 * 4)
                    = make_uint4(lo0[tau].x, lo1[tau].x, hi0[tau].x, hi1[tau].x);
                *(uint4*)(Anxt + tau * 640 + kcS * 128 + (j0 + 1) * 4)
                    = make_uint4(lo0[tau].y, lo1[tau].y, hi0[tau].y, hi1[tau].y);
            }
            if (t + 2 < TT) {
                const int tt2 = dir ? tt - 2 : tt + 2;
                #pragma unroll
                for (int tau = 0; tau < 2; tau++) {
                    const uint32_t* p0 = h0p[tau] + (size_t)tt2 * 32;
                    const uint32_t* p1 = p0 + (size_t)8 * TT * 32;
                    lo0[tau] = *(const uint2*)p0;
                    lo1[tau] = *(const uint2*)p1;
                    hi0[tau] = *(const uint2*)(p0 + 4);
                    hi1[tau] = *(const uint2*)(p1 + 4);
                }
            }
        }

        #pragma unroll
        for (int tau = 0; tau < 2; tau++) {
            uint32_t hp[2];
            float hlast[4];
            #pragma unroll
            for (int rh = 0; rh < 2; rh++) {
                float h0, h1;
                {
                    const int p = rh * 2;
                    const float ig = sigx(d[tau][0][p]);
                    const float fg = sigx(d[tau][1][p]);
                    const float gg = tanhx(d[tau][2][p]);
                    const float og = sigx(d[tau][3][p]);
                    const float c  = fg * cc[tau][p] + ig * gg;
                    h0 = og * tanhx(c); cc[tau][p] = c;
                }
                {
                    const int p = rh * 2 + 1;
                    const float ig = sigx(d[tau][0][p]);
                    const float fg = sigx(d[tau][1][p]);
                    const float gg = tanhx(d[tau][2][p]);
                    const float og = sigx(d[tau][3][p]);
                    const float c  = fg * cc[tau][p] + ig * gg;
                    h1 = og * tanhx(c); cc[tau][p] = c;
                }
                hp[rh] = bf2(h0, h1);
                hlast[rh * 2] = h0; hlast[rh * 2 + 1] = h1;
            }
            *(uint2*)(Anxt + tau * 640 + 4 * 128 + l * 4 + half * 2)
                = make_uint2(hp[0], hp[1]);

            if (t == TT - 1) {
                #pragma unroll
                for (int rh = 0; rh < 2; rh++) {
                    const int e0 = half * 8 + 2 * tig;
                    *(float2*)&g_h2[(ws + tau * 16 + gid + 8 * rh) * 32 + dir * 16 + e0]
                        = make_float2(hlast[rh * 2], hlast[rh * 2 + 1]);
                }
            }
        }

        __syncthreads();
    }
}

// ================= head: dense(8)+swish, dense(2)+sigmoid ================
__device__ __forceinline__ float sigf(float x) { return 1.0f / (1.0f + __expf(-x)); }

__global__ void head_kernel(
    const float* __restrict__ W3, const float* __restrict__ b3,
    const float* __restrict__ W4, const float* __restrict__ b4,
    float* __restrict__ out, int B)
{
    const int b = blockIdx.x * blockDim.x + threadIdx.x;
    if (b >= B) return;

    float xvv[32];
    #pragma unroll
    for (int i = 0; i < 32; i++) xvv[i] = g_h2[b * 32 + i];

    float y[8];
    #pragma unroll
    for (int o = 0; o < 8; o++) {
        float acc = b3[o];
        #pragma unroll
        for (int k = 0; k < 32; k++)
            acc = fmaf(xvv[k], W3[k * 8 + o], acc);
        y[o] = acc * sigf(acc);
    }

    #pragma unroll
    for (int m = 0; m < 2; m++) {
        float acc = b4[m];
        #pragma unroll
        for (int o = 0; o < 8; o++)
            acc = fmaf(y[o], W4[o * 2 + m], acc);
        out[b * 2 + m] = sigf(acc);
    }
}

// ================= launch ================
extern "C" void kernel_launch(void* const* d_in, const int* in_sizes, int n_in,
                              void* d_out, int out_size)
{
    const float* x   = (const float*)d_in[0];
    const float* W1f = (const float*)d_in[1];
    const float* U1f = (const float*)d_in[2];
    const float* b1f = (const float*)d_in[3];
    const float* W1b = (const float*)d_in[4];
    const float* U1b = (const float*)d_in[5];
    const float* b1b = (const float*)d_in[6];
    const float* W2f = (const float*)d_in[7];
    const float* U2f = (const float*)d_in[8];
    const float* b2f = (const float*)d_in[9];
    const float* W2b = (const float*)d_in[10];
    const float* U2b = (const float*)d_in[11];
    const float* b2b = (const float*)d_in[12];
    const float* W3  = (const float*)d_in[13];
    const float* b3  = (const float*)d_in[14];
    const float* W4  = (const float*)d_in[15];
    const float* b4  = (const float*)d_in[16];
    float* out = (float*)d_out;

    const int B = in_sizes[0] / (TT * 64);   // 4096

    lstm1_mma<<<dim3(B / 32, 2), 128>>>(x, W1f, U1f, b1f, W1b, U1b, b1b);
    lstm2_mma<<<dim3(B / 32, 2), 64>>>(W2f, U2f, b2f, W2b, U2b, b2b);
    head_kernel<<<(B + 255) / 256, 256>>>(W3, b3, W4, b4, out, B);
}

// round 10
// speedup vs baseline: 1.0429x; 1.0429x over previous
#include <cuda_runtime.h>
#include <cuda_bf16.h>
#include <stdint.h>

#define TT 128
#define MAXB 4096

// ---------------- scratch ----------------
__device__ uint32_t g_h1b[(size_t)MAXB * TT * 32];  // layer1 bidi out, bf16x2 [B][T][32]
__device__ float    g_h2[MAXB * 32];                // layer2 concat [B][32]

// ---------------- helpers ----------------
__device__ __forceinline__ uint32_t bf2(float lo, float hi) {
    uint32_t r;
    asm("cvt.rn.bf16x2.f32 %0, %1, %2;" : "=r"(r) : "f"(hi), "f"(lo));
    return r;
}
__device__ __forceinline__ uint32_t bf2p(float2 v) { return bf2(v.x, v.y); }
__device__ __forceinline__ float tanhx(float x) {
    float y; asm("tanh.approx.f32 %0, %1;" : "=f"(y) : "f"(x)); return y;
}
__device__ __forceinline__ float sigx(float x) {
    return fmaf(tanhx(x * 0.5f), 0.5f, 0.5f);
}
__device__ __forceinline__ void mma_bf16(float* d, const uint4& a, uint32_t b0, uint32_t b1) {
    asm volatile(
        "mma.sync.aligned.m16n8k16.row.col.f32.bf16.bf16.f32 "
        "{%0,%1,%2,%3},{%4,%5,%6,%7},{%8,%9},{%0,%1,%2,%3};"
        : "+f"(d[0]), "+f"(d[1]), "+f"(d[2]), "+f"(d[3])
        : "r"(a.x), "r"(a.y), "r"(a.z), "r"(a.w), "r"(b0), "r"(b1));
}

// ================= layer 1: H=32, KIN=64, K=96 (KC=6), seq out (bf16) ========
// (R8 kernel, unchanged: 4-way N-split, B in regs, A double-buffered, 1 bar/step)
__global__ void __launch_bounds__(128) lstm1_mma(
    const float* __restrict__ in,
    const float* __restrict__ Wf, const float* __restrict__ Uf, const float* __restrict__ bf_,
    const float* __restrict__ Wb, const float* __restrict__ Ub, const float* __restrict__ bb)
{
    __shared__ uint32_t Bsm[6 * 16 * 32 * 2];               // 24KB (init only)
    __shared__ __align__(16) uint32_t Asm[2 * 6 * 32 * 4];  // 6KB, 2 buffers
    __shared__ __align__(16) uint32_t houtS[2 * 16 * 18];   // 2.25KB, 2 buffers
    __shared__ float biasS[128];

    const int dir = blockIdx.y;
    const float* W    = dir ? Wb : Wf;
    const float* U    = dir ? Ub : Uf;
    const float* bias = dir ? bb : bf_;

    const int tid = threadIdx.x;
    const int q   = tid >> 5;
    const int l   = tid & 31;
    const int gid = l >> 2;
    const int tig = l & 3;

    for (int idx = tid; idx < 6 * 16 * 32 * 2; idx += 128) {
        const int which = idx & 1;
        const int lane  = (idx >> 1) & 31;
        const int nt    = (idx >> 6) & 15;
        const int kc    = idx >> 10;
        const int k = kc * 16 + which * 8 + 2 * (lane & 3);
        const int n = nt * 8 + (lane >> 2);
        const float v0 = (k     < 64) ? W[k * 128 + n]       : U[(k - 64) * 128 + n];
        const float v1 = (k + 1 < 64) ? W[(k + 1) * 128 + n] : U[(k - 63) * 128 + n];
        Bsm[idx] = bf2(v0, v1);
    }
    if (tid < 128) biasS[tid] = bias[tid];
    for (int idx = tid; idx < 256; idx += 128) Asm[512 + idx] = 0;
    __syncthreads();

    uint32_t Br[6][4][2];
    #pragma unroll
    for (int kc = 0; kc < 6; kc++)
        #pragma unroll
        for (int g = 0; g < 4; g++) {
            const int base = ((kc * 16 + g * 4 + q) * 32 + l) * 2;
            Br[kc][g][0] = Bsm[base];
            Br[kc][g][1] = Bsm[base + 1];
        }

    float2 bz[4];
    #pragma unroll
    for (int g = 0; g < 4; g++) {
        const int col = g * 32 + q * 8 + 2 * tig;
        bz[g] = make_float2(biasS[col], biasS[col + 1]);
    }

    const int ws = blockIdx.x * 16;
    const float* xs0 = in + (size_t)(ws + gid) * TT * 64 + q * 16 + 2 * tig;
    const float* xs1 = xs0 + (size_t)8 * TT * 64;
    uint32_t* AsA = Asm + q * 128 + l * 4;

    const int sF  = tid >> 3;
    const int ocF = tid & 7;

    float cc[4] = {0.f, 0.f, 0.f, 0.f};

    float2 xr0, xr1, xr2, xr3;
    {
        const int tt0 = dir ? TT - 1 : 0;
        xr0 = *(const float2*)(xs0 + (size_t)tt0 * 64);
        xr1 = *(const float2*)(xs1 + (size_t)tt0 * 64);
        xr2 = *(const float2*)(xs0 + (size_t)tt0 * 64 + 8);
        xr3 = *(const float2*)(xs1 + (size_t)tt0 * 64 + 8);
        *(uint4*)AsA = make_uint4(bf2p(xr0), bf2p(xr1), bf2p(xr2), bf2p(xr3));
        if (TT > 1) {
            const int tt1 = dir ? TT - 2 : 1;
            xr0 = *(const float2*)(xs0 + (size_t)tt1 * 64);
            xr1 = *(const float2*)(xs1 + (size_t)tt1 * 64);
            xr2 = *(const float2*)(xs0 + (size_t)tt1 * 64 + 8);
            xr3 = *(const float2*)(xs1 + (size_t)tt1 * 64 + 8);
        }
    }
    __syncthreads();

    for (int t = 0; t < TT; t++) {
        const int tt = dir ? TT - 1 - t : t;
        const uint32_t* Acur = Asm + (t & 1) * 768;
        uint32_t*       Anxt = Asm + ((t + 1) & 1) * 768;

        float d[4][4];
        #pragma unroll
        for (int g = 0; g < 4; g++) {
            d[g][0] = bz[g].x; d[g][1] = bz[g].y;
            d[g][2] = bz[g].x; d[g][3] = bz[g].y;
        }
        #pragma unroll
        for (int kc = 0; kc < 6; kc++) {
            const uint4 a = *((const uint4*)Acur + kc * 32 + l);
            #pragma unroll
            for (int g = 0; g < 4; g++)
                mma_bf16(d[g], a, Br[kc][g][0], Br[kc][g][1]);
        }

        if (t > 0) {
            const int tprev = dir ? tt + 1 : tt - 1;
            const uint2 hv = *(const uint2*)&houtS[((t - 1) & 1) * 288 + sF * 18 + ocF * 2];
            *(uint2*)&g_h1b[((size_t)(ws + sF) * TT + tprev) * 32 + dir * 16 + ocF * 2] = hv;
        }

        if (t + 1 < TT) {
            *(uint4*)(Anxt + q * 128 + l * 4)
                = make_uint4(bf2p(xr0), bf2p(xr1), bf2p(xr2), bf2p(xr3));
            if (t + 2 < TT) {
                const int tt2 = dir ? tt - 2 : tt + 2;
                xr0 = *(const float2*)(xs0 + (size_t)tt2 * 64);
                xr1 = *(const float2*)(xs1 + (size_t)tt2 * 64);
                xr2 = *(const float2*)(xs0 + (size_t)tt2 * 64 + 8);
                xr3 = *(const float2*)(xs1 + (size_t)tt2 * 64 + 8);
            }
        }

        uint32_t hp[2];
        #pragma unroll
        for (int rh = 0; rh < 2; rh++) {
            float h0, h1;
            {
                const int p = rh * 2;
                const float ig = sigx(d[0][p]);
                const float fg = sigx(d[1][p]);
                const float gg = tanhx(d[2][p]);
                const float og = sigx(d[3][p]);
                const float c  = fg * cc[p] + ig * gg;
                h0 = og * tanhx(c); cc[p] = c;
            }
            {
                const int p = rh * 2 + 1;
                const float ig = sigx(d[0][p]);
                const float fg = sigx(d[1][p]);
                const float gg = tanhx(d[2][p]);
                const float og = sigx(d[3][p]);
                const float c  = fg * cc[p] + ig * gg;
                h1 = og * tanhx(c); cc[p] = c;
            }
            hp[rh] = bf2(h0, h1);
            houtS[(t & 1) * 288 + (gid + 8 * rh) * 18 + q * 4 + tig] = hp[rh];
        }
        *(uint2*)(Anxt + (4 + (q >> 1)) * 128 + l * 4 + (q & 1) * 2)
            = make_uint2(hp[0], hp[1]);

        __syncthreads();
    }

    {
        const int tlast = dir ? 0 : TT - 1;
        const uint2 hv = *(const uint2*)&houtS[((TT - 1) & 1) * 288 + sF * 18 + ocF * 2];
        *(uint2*)&g_h1b[((size_t)(ws + sF) * TT + tlast) * 32 + dir * 16 + ocF * 2] = hv;
    }
}

// ================= layer 2: H=16, K=80 (KC=5), last-h only ===================
// NEW: gate-element INTERLEAVED B columns -> 4-way N-split, 4 warps per
// 16-sample group (2048 warps total). Block = 128 thr = 1 group; grid (B/16,2).
// Interleaved col C = e*4+g  (e in [0,16), g in [0,4)); tile nt covers elems
// {nt*2, nt*2+1} with ALL 4 gates. Warp q owns tiles {2q, 2q+1} (elems 4q..4q+3),
// 10 MMA/step. Gates of an element split across adjacent lanes -> 8 shfl.xor(1)
// per step regroups z. h-feedback via 2x st.shared.b16 into A-fragment slots.
__global__ void __launch_bounds__(128) lstm2_mma(
    const float* __restrict__ W2f, const float* __restrict__ U2f, const float* __restrict__ b2f,
    const float* __restrict__ W2b, const float* __restrict__ U2b, const float* __restrict__ b2b)
{
    __shared__ uint32_t Bsm[5 * 8 * 32 * 2];               // 10KB (init only)
    __shared__ __align__(16) uint32_t Asm[2 * 5 * 128];    // 5KB, 2 buffers
    __shared__ float biasS[64];

    const int dir = blockIdx.y;
    const float* W    = dir ? W2b : W2f;
    const float* U    = dir ? U2b : U2f;
    const float* bias = dir ? b2b : b2f;

    const int tid = threadIdx.x;
    const int q   = tid >> 5;
    const int l   = tid & 31;
    const int gid = l >> 2;
    const int tig = l & 3;

    // ---- build B fragments with interleaved columns ----
    for (int idx = tid; idx < 5 * 8 * 32 * 2; idx += 128) {
        const int which = idx & 1;
        const int lane  = (idx >> 1) & 31;
        const int nt    = (idx >> 6) & 7;
        const int kc    = idx >> 9;
        const int C = nt * 8 + (lane >> 2);        // interleaved col
        const int e = C >> 2, g = C & 3;
        const int n = g * 16 + e;                  // source col in W/U
        const int k = kc * 16 + which * 8 + 2 * (lane & 3);
        const float v0 = (k     < 64) ? W[k * 64 + n]       : U[(k - 64) * 64 + n];
        const float v1 = (k + 1 < 64) ? W[(k + 1) * 64 + n] : U[(k - 63) * 64 + n];
        Bsm[idx] = bf2(v0, v1);
    }
    if (tid < 64) biasS[tid] = bias[tid];
    if (tid < 128) Asm[4 * 128 + tid] = 0;   // zero h region of buffer 0
    __syncthreads();

    // ---- B to registers: warp q, tiles 2q, 2q+1 ----
    uint32_t Br[5][2][2];
    #pragma unroll
    for (int kc = 0; kc < 5; kc++)
        #pragma unroll
        for (int tt2 = 0; tt2 < 2; tt2++) {
            const int base = ((kc * 8 + 2 * q + tt2) * 32 + l) * 2;
            Br[kc][tt2][0] = Bsm[base];
            Br[kc][tt2][1] = Bsm[base + 1];
        }

    float2 bz[2];
    #pragma unroll
    for (int tt2 = 0; tt2 < 2; tt2++) {
        const int C0 = (2 * q + tt2) * 8 + 2 * tig;   // even
        const int e  = C0 >> 2, g0 = C0 & 3;
        bz[tt2] = make_float2(biasS[g0 * 16 + e], biasS[(g0 + 1) * 16 + e]);
    }

    const int ws = blockIdx.x * 16;
    const int eMine = 4 * q + 2 * (tig & 1) + (tig >> 1);

    // feedback byte offsets (within a buffer) for rows gid and gid+8, elem eMine
    const int fbIdx0 = (gid * 16 + ((eMine & 7) >> 1) * 4 + ((eMine >> 3) << 1)) * 4
                       + (eMine & 1) * 2;
    const int fbIdx1 = fbIdx0 + 4;   // rh = 1 -> +1 u32

    // ---- staging (threads 0..63): R8 mapping ----
    const bool stg = tid < 64;
    const int kcS  = tid >> 4;            // 0..3 for tid<64
    const int gidS = (tid & 15) >> 1;
    const int tp   = tid & 1;
    const int j0   = gidS * 4 + 2 * tp;
    const uint32_t* h0p = g_h1b + (size_t)(ws + gidS) * TT * 32 + kcS * 8 + 2 * tp;
    const uint32_t* h1p = h0p + (size_t)8 * TT * 32;

    float cc[2] = {0.f, 0.f};

    uint2 lo0, lo1, hi0, hi1;
    if (stg) {
        const int tt0 = dir ? TT - 1 : 0;
        lo0 = *(const uint2*)(h0p + (size_t)tt0 * 32);
        lo1 = *(const uint2*)(h1p + (size_t)tt0 * 32);
        hi0 = *(const uint2*)(h0p + (size_t)tt0 * 32 + 4);
        hi1 = *(const uint2*)(h1p + (size_t)tt0 * 32 + 4);
        *(uint4*)(Asm + kcS * 128 + j0 * 4)       = make_uint4(lo0.x, lo1.x, hi0.x, hi1.x);
        *(uint4*)(Asm + kcS * 128 + (j0 + 1) * 4) = make_uint4(lo0.y, lo1.y, hi0.y, hi1.y);
        const int tt1 = dir ? TT - 2 : 1;
        lo0 = *(const uint2*)(h0p + (size_t)tt1 * 32);
        lo1 = *(const uint2*)(h1p + (size_t)tt1 * 32);
        hi0 = *(const uint2*)(h0p + (size_t)tt1 * 32 + 4);
        hi1 = *(const uint2*)(h1p + (size_t)tt1 * 32 + 4);
    }
    __syncthreads();

    for (int t = 0; t < TT; t++) {
        const int tt = dir ? TT - 1 - t : t;
        const uint32_t* Acur = Asm + (t & 1) * 640;
        uint32_t*       Anxt = Asm + ((t + 1) & 1) * 640;

        // ---- MMA: 2 tiles x 5 kc ----
        float d[2][4];
        #pragma unroll
        for (int tt2 = 0; tt2 < 2; tt2++) {
            d[tt2][0] = bz[tt2].x; d[tt2][1] = bz[tt2].y;
            d[tt2][2] = bz[tt2].x; d[tt2][3] = bz[tt2].y;
        }
        #pragma unroll
        for (int kc = 0; kc < 5; kc++) {
            const uint4 a = *((const uint4*)Acur + kc * 32 + l);
            mma_bf16(d[0], a, Br[kc][0][0], Br[kc][0][1]);
            mma_bf16(d[1], a, Br[kc][1][0], Br[kc][1][1]);
        }

        // ---- stage x_{t+1}; prefetch x_{t+2} ----
        if (t + 1 < TT && stg) {
            *(uint4*)(Anxt + kcS * 128 + j0 * 4)       = make_uint4(lo0.x, lo1.x, hi0.x, hi1.x);
            *(uint4*)(Anxt + kcS * 128 + (j0 + 1) * 4) = make_uint4(lo0.y, lo1.y, hi0.y, hi1.y);
            if (t + 2 < TT) {
                const int tt2i = dir ? tt - 2 : tt + 2;
                lo0 = *(const uint2*)(h0p + (size_t)tt2i * 32);
                lo1 = *(const uint2*)(h1p + (size_t)tt2i * 32);
                hi0 = *(const uint2*)(h0p + (size_t)tt2i * 32 + 4);
                hi1 = *(const uint2*)(h1p + (size_t)tt2i * 32 + 4);
            }
        }

        // ---- z regroup: gates (g,o)/(i,f) live in adjacent lanes ----
        const float e00 = __shfl_xor_sync(0xffffffffu, d[0][0], 1);
        const float e01 = __shfl_xor_sync(0xffffffffu, d[0][1], 1);
        const float e02 = __shfl_xor_sync(0xffffffffu, d[0][2], 1);
        const float e03 = __shfl_xor_sync(0xffffffffu, d[0][3], 1);
        const float e10 = __shfl_xor_sync(0xffffffffu, d[1][0], 1);
        const float e11 = __shfl_xor_sync(0xffffffffu, d[1][1], 1);
        const float e12 = __shfl_xor_sync(0xffffffffu, d[1][2], 1);
        const float e13 = __shfl_xor_sync(0xffffffffu, d[1][3], 1);

        float zi0, zf0, zg0, zo0, zi1, zf1, zg1, zo1;
        if ((tig & 1) == 0) {   // even lane-pair member: owns tile 0 (i,f), gets (g,o)
            zi0 = d[0][0]; zf0 = d[0][1]; zg0 = e00; zo0 = e01;
            zi1 = d[0][2]; zf1 = d[0][3]; zg1 = e02; zo1 = e03;
        } else {                // odd: owns tile 1 (g,o), gets (i,f)
            zi0 = e10; zf0 = e11; zg0 = d[1][0]; zo0 = d[1][1];
            zi1 = e12; zf1 = e13; zg1 = d[1][2]; zo1 = d[1][3];
        }

        // ---- activations (elem eMine, rows gid / gid+8) ----
        const float c0 = sigx(zf0) * cc[0] + sigx(zi0) * tanhx(zg0);
        const float h0 = sigx(zo0) * tanhx(c0);
        const float c1 = sigx(zf1) * cc[1] + sigx(zi1) * tanhx(zg1);
        const float h1 = sigx(zo1) * tanhx(c1);
        cc[0] = c0; cc[1] = c1;

        // ---- h feedback into A[(t+1)&1] kc4 (b16 scalar stores) ----
        char* fb = (char*)(Anxt + 4 * 128);
        *(__nv_bfloat16*)(fb + fbIdx0) = __float2bfloat16(h0);
        *(__nv_bfloat16*)(fb + fbIdx1) = __float2bfloat16(h1);

        if (t == TT - 1) {
            g_h2[(ws + gid)     * 32 + dir * 16 + eMine] = h0;
            g_h2[(ws + gid + 8) * 32 + dir * 16 + eMine] = h1;
        }

        __syncthreads();
    }
}

// ================= head: dense(8)+swish, dense(2)+sigmoid ================
__device__ __forceinline__ float sigf(float x) { return 1.0f / (1.0f + __expf(-x)); }

__global__ void head_kernel(
    const float* __restrict__ W3, const float* __restrict__ b3,
    const float* __restrict__ W4, const float* __restrict__ b4,
    float* __restrict__ out, int B)
{
    const int b = blockIdx.x * blockDim.x + threadIdx.x;
    if (b >= B) return;

    float xvv[32];
    #pragma unroll
    for (int i = 0; i < 32; i++) xvv[i] = g_h2[b * 32 + i];

    float y[8];
    #pragma unroll
    for (int o = 0; o < 8; o++) {
        float acc = b3[o];
        #pragma unroll
        for (int k = 0; k < 32; k++)
            acc = fmaf(xvv[k], W3[k * 8 + o], acc);
        y[o] = acc * sigf(acc);
    }

    #pragma unroll
    for (int m = 0; m < 2; m++) {
        float acc = b4[m];
        #pragma unroll
        for (int o = 0; o < 8; o++)
            acc = fmaf(y[o], W4[o * 2 + m], acc);
        out[b * 2 + m] = sigf(acc);
    }
}

// ================= launch ================
extern "C" void kernel_launch(void* const* d_in, const int* in_sizes, int n_in,
                              void* d_out, int out_size)
{
    const float* x   = (const float*)d_in[0];
    const float* W1f = (const float*)d_in[1];
    const float* U1f = (const float*)d_in[2];
    const float* b1f = (const float*)d_in[3];
    const float* W1b = (const float*)d_in[4];
    const float* U1b = (const float*)d_in[5];
    const float* b1b = (const float*)d_in[6];
    const float* W2f = (const float*)d_in[7];
    const float* U2f = (const float*)d_in[8];
    const float* b2f = (const float*)d_in[9];
    const float* W2b = (const float*)d_in[10];
    const float* U2b = (const float*)d_in[11];
    const float* b2b = (const float*)d_in[12];
    const float* W3  = (const float*)d_in[13];
    const float* b3  = (const float*)d_in[14];
    const float* W4  = (const float*)d_in[15];
    const float* b4  = (const float*)d_in[16];
    float* out = (float*)d_out;

    const int B = in_sizes[0] / (TT * 64);   // 4096

    lstm1_mma<<<dim3(B / 16, 2), 128>>>(x, W1f, U1f, b1f, W1b, U1b, b1b);
    lstm2_mma<<<dim3(B / 16, 2), 128>>>(W2f, U2f, b2f, W2b, U2b, b2b);
    head_kernel<<<(B + 255) / 256, 256>>>(W3, b3, W4, b4, out, B);
}

// round 11
// speedup vs baseline: 1.1368x; 1.0900x over previous
#include <cuda_runtime.h>
#include <cuda_bf16.h>
#include <stdint.h>

#define TT 128
#define MAXB 4096

// ---------------- scratch ----------------
__device__ uint32_t g_h1b[(size_t)MAXB * TT * 32];  // layer1 bidi out, bf16x2 [B][T][32]
__device__ float    g_h2[MAXB * 32];                // layer2 concat [B][32]

// ---------------- helpers ----------------
__device__ __forceinline__ uint32_t bf2(float lo, float hi) {
    uint32_t r;
    asm("cvt.rn.bf16x2.f32 %0, %1, %2;" : "=r"(r) : "f"(hi), "f"(lo));
    return r;
}
__device__ __forceinline__ float tanhx(float x) {
    float y; asm("tanh.approx.f32 %0, %1;" : "=f"(y) : "f"(x)); return y;
}
__device__ __forceinline__ float sigx(float x) {
    return fmaf(tanhx(x * 0.5f), 0.5f, 0.5f);
}
__device__ __forceinline__ void mma_bf16(float* d, const uint4& a, uint32_t b0, uint32_t b1) {
    asm volatile(
        "mma.sync.aligned.m16n8k16.row.col.f32.bf16.bf16.f32 "
        "{%0,%1,%2,%3},{%4,%5,%6,%7},{%8,%9},{%0,%1,%2,%3};"
        : "+f"(d[0]), "+f"(d[1]), "+f"(d[2]), "+f"(d[3])
        : "r"(a.x), "r"(a.y), "r"(a.z), "r"(a.w), "r"(b0), "r"(b1));
}

// ================= layer 1: H=32, KIN=64, K=96 (KC=6), seq out (bf16) ========
// R8 structure; ONLY staging changed: x loaded as 2x LDG.128 per step (rows
// gid, gid+8, 16 contiguous floats each) then redistributed to the fragment
// owners via shfl (L1 wavefronts for x: 32 -> 16 per warp-step).
__global__ void __launch_bounds__(128) lstm1_mma(
    const float* __restrict__ in,
    const float* __restrict__ Wf, const float* __restrict__ Uf, const float* __restrict__ bf_,
    const float* __restrict__ Wb, const float* __restrict__ Ub, const float* __restrict__ bb)
{
    __shared__ uint32_t Bsm[6 * 16 * 32 * 2];               // 24KB (init only)
    __shared__ __align__(16) uint32_t Asm[2 * 6 * 32 * 4];  // 6KB, 2 buffers
    __shared__ __align__(16) uint32_t houtS[2 * 16 * 18];   // 2.25KB, 2 buffers
    __shared__ float biasS[128];

    const int dir = blockIdx.y;
    const float* W    = dir ? Wb : Wf;
    const float* U    = dir ? Ub : Uf;
    const float* bias = dir ? bb : bf_;

    const int tid = threadIdx.x;
    const int q   = tid >> 5;
    const int l   = tid & 31;
    const int gid = l >> 2;
    const int tig = l & 3;

    for (int idx = tid; idx < 6 * 16 * 32 * 2; idx += 128) {
        const int which = idx & 1;
        const int lane  = (idx >> 1) & 31;
        const int nt    = (idx >> 6) & 15;
        const int kc    = idx >> 10;
        const int k = kc * 16 + which * 8 + 2 * (lane & 3);
        const int n = nt * 8 + (lane >> 2);
        const float v0 = (k     < 64) ? W[k * 128 + n]       : U[(k - 64) * 128 + n];
        const float v1 = (k + 1 < 64) ? W[(k + 1) * 128 + n] : U[(k - 63) * 128 + n];
        Bsm[idx] = bf2(v0, v1);
    }
    if (tid < 128) biasS[tid] = bias[tid];
    for (int idx = tid; idx < 256; idx += 128) Asm[512 + idx] = 0;
    __syncthreads();

    uint32_t Br[6][4][2];
    #pragma unroll
    for (int kc = 0; kc < 6; kc++)
        #pragma unroll
        for (int g = 0; g < 4; g++) {
            const int base = ((kc * 16 + g * 4 + q) * 32 + l) * 2;
            Br[kc][g][0] = Bsm[base];
            Br[kc][g][1] = Bsm[base + 1];
        }

    float2 bz[4];
    #pragma unroll
    for (int g = 0; g < 4; g++) {
        const int col = g * 32 + q * 8 + 2 * tig;
        bz[g] = make_float2(biasS[col], biasS[col + 1]);
    }

    const int ws = blockIdx.x * 16;
    // wide x pointers: 16 contiguous floats per row per warp-chunk
    const float* xL0 = in + (size_t)(ws + gid) * TT * 64 + q * 16 + 4 * tig;
    const float* xL1 = xL0 + (size_t)8 * TT * 64;

    const int srcLo = (l & ~3) | (tig >> 1);
    const int srcHi = srcLo + 2;
    const bool oddT = (tig & 1) != 0;

    const int sF  = tid >> 3;
    const int ocF = tid & 7;

    float cc[4] = {0.f, 0.f, 0.f, 0.f};

    // stage-from-registers helper pattern (inlined below twice)
    float4 v0, v1;   // prefetched raw x (rows gid, gid+8; 4 floats each)

    {   // prologue: stage x_0 into buffer 0; prefetch x_1
        const int tt0 = dir ? TT - 1 : 0;
        v0 = *(const float4*)(xL0 + (size_t)tt0 * 64);
        v1 = *(const float4*)(xL1 + (size_t)tt0 * 64);
        const uint32_t pa0 = bf2(v0.x, v0.y), pa1 = bf2(v0.z, v0.w);
        const uint32_t pb0 = bf2(v1.x, v1.y), pb1 = bf2(v1.z, v1.w);
        const uint32_t a0l = __shfl_sync(0xffffffffu, pa0, srcLo);
        const uint32_t a1l = __shfl_sync(0xffffffffu, pa1, srcLo);
        const uint32_t b0l = __shfl_sync(0xffffffffu, pb0, srcLo);
        const uint32_t b1l = __shfl_sync(0xffffffffu, pb1, srcLo);
        const uint32_t a0h = __shfl_sync(0xffffffffu, pa0, srcHi);
        const uint32_t a1h = __shfl_sync(0xffffffffu, pa1, srcHi);
        const uint32_t b0h = __shfl_sync(0xffffffffu, pb0, srcHi);
        const uint32_t b1h = __shfl_sync(0xffffffffu, pb1, srcHi);
        *(uint4*)(Asm + q * 128 + l * 4) = make_uint4(
            oddT ? a1l : a0l, oddT ? b1l : b0l,
            oddT ? a1h : a0h, oddT ? b1h : b0h);
        if (TT > 1) {
            const int tt1 = dir ? TT - 2 : 1;
            v0 = *(const float4*)(xL0 + (size_t)tt1 * 64);
            v1 = *(const float4*)(xL1 + (size_t)tt1 * 64);
        }
    }
    __syncthreads();

    for (int t = 0; t < TT; t++) {
        const int tt = dir ? TT - 1 - t : t;
        const uint32_t* Acur = Asm + (t & 1) * 768;
        uint32_t*       Anxt = Asm + ((t + 1) & 1) * 768;

        float d[4][4];
        #pragma unroll
        for (int g = 0; g < 4; g++) {
            d[g][0] = bz[g].x; d[g][1] = bz[g].y;
            d[g][2] = bz[g].x; d[g][3] = bz[g].y;
        }
        #pragma unroll
        for (int kc = 0; kc < 6; kc++) {
            const uint4 a = *((const uint4*)Acur + kc * 32 + l);
            #pragma unroll
            for (int g = 0; g < 4; g++)
                mma_bf16(d[g], a, Br[kc][g][0], Br[kc][g][1]);
        }

        if (t > 0) {
            const int tprev = dir ? tt + 1 : tt - 1;
            const uint2 hv = *(const uint2*)&houtS[((t - 1) & 1) * 288 + sF * 18 + ocF * 2];
            *(uint2*)&g_h1b[((size_t)(ws + sF) * TT + tprev) * 32 + dir * 16 + ocF * 2] = hv;
        }

        if (t + 1 < TT) {
            const uint32_t pa0 = bf2(v0.x, v0.y), pa1 = bf2(v0.z, v0.w);
            const uint32_t pb0 = bf2(v1.x, v1.y), pb1 = bf2(v1.z, v1.w);
            const uint32_t a0l = __shfl_sync(0xffffffffu, pa0, srcLo);
            const uint32_t a1l = __shfl_sync(0xffffffffu, pa1, srcLo);
            const uint32_t b0l = __shfl_sync(0xffffffffu, pb0, srcLo);
            const uint32_t b1l = __shfl_sync(0xffffffffu, pb1, srcLo);
            const uint32_t a0h = __shfl_sync(0xffffffffu, pa0, srcHi);
            const uint32_t a1h = __shfl_sync(0xffffffffu, pa1, srcHi);
            const uint32_t b0h = __shfl_sync(0xffffffffu, pb0, srcHi);
            const uint32_t b1h = __shfl_sync(0xffffffffu, pb1, srcHi);
            *(uint4*)(Anxt + q * 128 + l * 4) = make_uint4(
                oddT ? a1l : a0l, oddT ? b1l : b0l,
                oddT ? a1h : a0h, oddT ? b1h : b0h);
            if (t + 2 < TT) {
                const int tt2 = dir ? tt - 2 : tt + 2;
                v0 = *(const float4*)(xL0 + (size_t)tt2 * 64);
                v1 = *(const float4*)(xL1 + (size_t)tt2 * 64);
            }
        }

        uint32_t hp[2];
        #pragma unroll
        for (int rh = 0; rh < 2; rh++) {
            float h0, h1;
            {
                const int p = rh * 2;
                const float ig = sigx(d[0][p]);
                const float fg = sigx(d[1][p]);
                const float gg = tanhx(d[2][p]);
                const float og = sigx(d[3][p]);
                const float c  = fg * cc[p] + ig * gg;
                h0 = og * tanhx(c); cc[p] = c;
            }
            {
                const int p = rh * 2 + 1;
                const float ig = sigx(d[0][p]);
                const float fg = sigx(d[1][p]);
                const float gg = tanhx(d[2][p]);
                const float og = sigx(d[3][p]);
                const float c  = fg * cc[p] + ig * gg;
                h1 = og * tanhx(c); cc[p] = c;
            }
            hp[rh] = bf2(h0, h1);
            houtS[(t & 1) * 288 + (gid + 8 * rh) * 18 + q * 4 + tig] = hp[rh];
        }
        *(uint2*)(Anxt + (4 + (q >> 1)) * 128 + l * 4 + (q & 1) * 2)
            = make_uint2(hp[0], hp[1]);

        __syncthreads();
    }

    {
        const int tlast = dir ? 0 : TT - 1;
        const uint2 hv = *(const uint2*)&houtS[((TT - 1) & 1) * 288 + sF * 18 + ocF * 2];
        *(uint2*)&g_h1b[((size_t)(ws + sF) * TT + tlast) * 32 + dir * 16 + ocF * 2] = hv;
    }
}

// ================= layer 2: H=16, K=80 (KC=5), last-h only, M=16 =============
// R8 lstm2 structure with M=16 per 2-warp block (tau removed): 1024 warps.
// Block = 64 thr = 2 warps owning 16 samples; grid (B/16, 2).
// Warp half: gate n-tiles g*2+half (20 MMA/step). B in regs. A double-buffered;
// one __syncthreads per step. Staging: pure u32 copies from g_h1b.
__global__ void __launch_bounds__(64) lstm2_mma(
    const float* __restrict__ W2f, const float* __restrict__ U2f, const float* __restrict__ b2f,
    const float* __restrict__ W2b, const float* __restrict__ U2b, const float* __restrict__ b2b)
{
    __shared__ uint32_t Bsm[5 * 8 * 32 * 2];               // 10KB (init only)
    __shared__ __align__(16) uint32_t Asm[2 * 5 * 128];    // 5KB, 2 buffers
    __shared__ float biasS[64];

    const int dir = blockIdx.y;
    const float* W    = dir ? W2b : W2f;
    const float* U    = dir ? U2b : U2f;
    const float* bias = dir ? b2b : b2f;

    const int tid  = threadIdx.x;
    const int half = tid >> 5;
    const int l    = tid & 31;
    const int gid  = l >> 2;
    const int tig  = l & 3;

    for (int idx = tid; idx < 5 * 8 * 32 * 2; idx += 64) {
        const int which = idx & 1;
        const int lane  = (idx >> 1) & 31;
        const int nt    = (idx >> 6) & 7;
        const int kc    = idx >> 9;
        const int k = kc * 16 + which * 8 + 2 * (lane & 3);
        const int n = nt * 8 + (lane >> 2);
        const float v0 = (k     < 64) ? W[k * 64 + n]       : U[(k - 64) * 64 + n];
        const float v1 = (k + 1 < 64) ? W[(k + 1) * 64 + n] : U[(k - 63) * 64 + n];
        Bsm[idx] = bf2(v0, v1);
    }
    if (tid < 64) biasS[tid] = bias[tid];
    for (int idx = tid; idx < 128; idx += 64) Asm[4 * 128 + idx] = 0;  // h region buf0
    __syncthreads();

    uint32_t Br[5][4][2];
    #pragma unroll
    for (int kc = 0; kc < 5; kc++)
        #pragma unroll
        for (int g = 0; g < 4; g++) {
            const int base = ((kc * 8 + g * 2 + half) * 32 + l) * 2;
            Br[kc][g][0] = Bsm[base];
            Br[kc][g][1] = Bsm[base + 1];
        }

    float2 bz[4];
    #pragma unroll
    for (int g = 0; g < 4; g++) {
        const int col = g * 16 + half * 8 + 2 * tig;
        bz[g] = make_float2(biasS[col], biasS[col + 1]);
    }

    const int ws = blockIdx.x * 16;

    // staging: thread tid (0-63) -> kcS (0-3), gidS (0-7), tp (0-1)
    const int kcS  = tid >> 4;
    const int gidS = (tid & 15) >> 1;
    const int tp   = tid & 1;
    const int j0   = gidS * 4 + 2 * tp;
    const uint32_t* h0p = g_h1b + (size_t)(ws + gidS) * TT * 32 + kcS * 8 + 2 * tp;
    const uint32_t* h1p = h0p + (size_t)8 * TT * 32;

    float cc[4] = {0.f, 0.f, 0.f, 0.f};

    uint2 lo0, lo1, hi0, hi1;
    {
        const int tt0 = dir ? TT - 1 : 0;
        lo0 = *(const uint2*)(h0p + (size_t)tt0 * 32);
        lo1 = *(const uint2*)(h1p + (size_t)tt0 * 32);
        hi0 = *(const uint2*)(h0p + (size_t)tt0 * 32 + 4);
        hi1 = *(const uint2*)(h1p + (size_t)tt0 * 32 + 4);
        *(uint4*)(Asm + kcS * 128 + j0 * 4)       = make_uint4(lo0.x, lo1.x, hi0.x, hi1.x);
        *(uint4*)(Asm + kcS * 128 + (j0 + 1) * 4) = make_uint4(lo0.y, lo1.y, hi0.y, hi1.y);
        const int tt1 = dir ? TT - 2 : 1;
        lo0 = *(const uint2*)(h0p + (size_t)tt1 * 32);
        lo1 = *(const uint2*)(h1p + (size_t)tt1 * 32);
        hi0 = *(const uint2*)(h0p + (size_t)tt1 * 32 + 4);
        hi1 = *(const uint2*)(h1p + (size_t)tt1 * 32 + 4);
    }
    __syncthreads();

    for (int t = 0; t < TT; t++) {
        const int tt = dir ? TT - 1 - t : t;
        const uint32_t* Acur = Asm + (t & 1) * 640;
        uint32_t*       Anxt = Asm + ((t + 1) & 1) * 640;

        float d[4][4];
        #pragma unroll
        for (int g = 0; g < 4; g++) {
            d[g][0] = bz[g].x; d[g][1] = bz[g].y;
            d[g][2] = bz[g].x; d[g][3] = bz[g].y;
        }
        #pragma unroll
        for (int kc = 0; kc < 5; kc++) {
            const uint4 a = *((const uint4*)Acur + kc * 32 + l);
            #pragma unroll
            for (int g = 0; g < 4; g++)
                mma_bf16(d[g], a, Br[kc][g][0], Br[kc][g][1]);
        }

        if (t + 1 < TT) {
            *(uint4*)(Anxt + kcS * 128 + j0 * 4)       = make_uint4(lo0.x, lo1.x, hi0.x, hi1.x);
            *(uint4*)(Anxt + kcS * 128 + (j0 + 1) * 4) = make_uint4(lo0.y, lo1.y, hi0.y, hi1.y);
            if (t + 2 < TT) {
                const int tt2 = dir ? tt - 2 : tt + 2;
                lo0 = *(const uint2*)(h0p + (size_t)tt2 * 32);
                lo1 = *(const uint2*)(h1p + (size_t)tt2 * 32);
                hi0 = *(const uint2*)(h0p + (size_t)tt2 * 32 + 4);
                hi1 = *(const uint2*)(h1p + (size_t)tt2 * 32 + 4);
            }
        }

        uint32_t hp[2];
        float hlast[4];
        #pragma unroll
        for (int rh = 0; rh < 2; rh++) {
            float h0, h1;
            {
                const int p = rh * 2;
                const float ig = sigx(d[0][p]);
                const float fg = sigx(d[1][p]);
                const float gg = tanhx(d[2][p]);
                const float og = sigx(d[3][p]);
                const float c  = fg * cc[p] + ig * gg;
                h0 = og * tanhx(c); cc[p] = c;
            }
            {
                const int p = rh * 2 + 1;
                const float ig = sigx(d[0][p]);
                const float fg = sigx(d[1][p]);
                const float gg = tanhx(d[2][p]);
                const float og = sigx(d[3][p]);
                const float c  = fg * cc[p] + ig * gg;
                h1 = og * tanhx(c); cc[p] = c;
            }
            hp[rh] = bf2(h0, h1);
            hlast[rh * 2] = h0; hlast[rh * 2 + 1] = h1;
        }
        *(uint2*)(Anxt + 4 * 128 + l * 4 + half * 2) = make_uint2(hp[0], hp[1]);

        if (t == TT - 1) {
            #pragma unroll
            for (int rh = 0; rh < 2; rh++) {
                const int e0 = half * 8 + 2 * tig;
                *(float2*)&g_h2[(ws + gid + 8 * rh) * 32 + dir * 16 + e0]
                    = make_float2(hlast[rh * 2], hlast[rh * 2 + 1]);
            }
        }

        __syncthreads();
    }
}

// ================= head: dense(8)+swish, dense(2)+sigmoid ================
__device__ __forceinline__ float sigf(float x) { return 1.0f / (1.0f + __expf(-x)); }

__global__ void head_kernel(
    const float* __restrict__ W3, const float* __restrict__ b3,
    const float* __restrict__ W4, const float* __restrict__ b4,
    float* __restrict__ out, int B)
{
    const int b = blockIdx.x * blockDim.x + threadIdx.x;
    if (b >= B) return;

    float xvv[32];
    #pragma unroll
    for (int i = 0; i < 32; i++) xvv[i] = g_h2[b * 32 + i];

    float y[8];
    #pragma unroll
    for (int o = 0; o < 8; o++) {
        float acc = b3[o];
        #pragma unroll
        for (int k = 0; k < 32; k++)
            acc = fmaf(xvv[k], W3[k * 8 + o], acc);
        y[o] = acc * sigf(acc);
    }

    #pragma unroll
    for (int m = 0; m < 2; m++) {
        float acc = b4[m];
        #pragma unroll
        for (int o = 0; o < 8; o++)
            acc = fmaf(y[o], W4[o * 2 + m], acc);
        out[b * 2 + m] = sigf(acc);
    }
}

// ================= launch ================
extern "C" void kernel_launch(void* const* d_in, const int* in_sizes, int n_in,
                              void* d_out, int out_size)
{
    const float* x   = (const float*)d_in[0];
    const float* W1f = (const float*)d_in[1];
    const float* U1f = (const float*)d_in[2];
    const float* b1f = (const float*)d_in[3];
    const float* W1b = (const float*)d_in[4];
    const float* U1b = (const float*)d_in[5];
    const float* b1b = (const float*)d_in[6];
    const float* W2f = (const float*)d_in[7];
    const float* U2f = (const float*)d_in[8];
    const float* b2f = (const float*)d_in[9];
    const float* W2b = (const float*)d_in[10];
    const float* U2b = (const float*)d_in[11];
    const float* b2b = (const float*)d_in[12];
    const float* W3  = (const float*)d_in[13];
    const float* b3  = (const float*)d_in[14];
    const float* W4  = (const float*)d_in[15];
    const float* b4  = (const float*)d_in[16];
    float* out = (float*)d_out;

    const int B = in_sizes[0] / (TT * 64);   // 4096

    lstm1_mma<<<dim3(B / 16, 2), 128>>>(x, W1f, U1f, b1f, W1b, U1b, b1b);
    lstm2_mma<<<dim3(B / 16, 2), 64>>>(W2f, U2f, b2f, W2b, U2b, b2b);
    head_kernel<<<(B + 255) / 256, 256>>>(W3, b3, W4, b4, out, B);
}